// round 6
// baseline (speedup 1.0000x reference)
#include <cuda_runtime.h>
#include <cstdint>
#include <cstddef>

#define Bb 32
#define Nn 1024
#define DIM 512
#define Hh 8
#define DHd 64
#define SCALE 0.125f

// Scratch (device globals: allocation-free per harness rules)
__device__ float g_Q[Bb*Hh*Nn*DHd];   // [b,h,n,d]
__device__ float g_K[Bb*Hh*Nn*DHd];
__device__ float g_V[Bb*Hh*Nn*DHd];
__device__ float g_O[Bb*Nn*Hh*DHd];   // [b,n,h*64+d]

__device__ __forceinline__ float tf32r(float x){
    unsigned r; asm("cvt.rna.tf32.f32 %0, %1;" : "=r"(r) : "f"(x));
    return __uint_as_float(r);
}
__device__ __forceinline__ unsigned fu(float x){ return __float_as_uint(x); }

// D += A(16x8,row) * B(8x8,col)  tf32
__device__ __forceinline__ void mma8(float* d, const unsigned* a, const unsigned* b){
    asm volatile(
        "mma.sync.aligned.m16n8k8.row.col.f32.tf32.tf32.f32 "
        "{%0,%1,%2,%3},{%4,%5,%6,%7},{%8,%9},{%0,%1,%2,%3};\n"
        : "+f"(d[0]), "+f"(d[1]), "+f"(d[2]), "+f"(d[3])
        : "r"(a[0]), "r"(a[1]), "r"(a[2]), "r"(a[3]), "r"(b[0]), "r"(b[1]));
}

// ============================================================================
// Kernel 1: QKV GEMM.  C[32768,1536] = x[32768,512] @ W_qkv[512,1536]
// (unchanged from round 1 — known 361us)
// ============================================================================
__global__ __launch_bounds__(256) void qkv_gemm_kernel(
    const float* __restrict__ A, const float* __restrict__ W)
{
    __shared__ float As[128*36];
    __shared__ float Bs[32*136];
    const int tid = threadIdx.x, lane = tid & 31, w = tid >> 5;
    const int gr = lane >> 2, gc = lane & 3;
    const int wm = w & 1, wn = w >> 1;
    const int mBase = blockIdx.y * 128, nBase = blockIdx.x * 128;

    float acc[4][4][4];
    #pragma unroll
    for (int i=0;i<4;i++)
        #pragma unroll
        for (int j=0;j<4;j++)
            #pragma unroll
            for (int c=0;c<4;c++) acc[i][j][c] = 0.f;

    for (int kt = 0; kt < 512; kt += 32){
        #pragma unroll
        for (int ii = 0; ii < 4; ii++){
            int i = tid + ii*256;
            int r = i >> 3, c = (i & 7) << 2;
            float4 v = *(const float4*)(A + (size_t)(mBase + r)*512 + kt + c);
            float* p = As + r*36 + c;
            p[0]=tf32r(v.x); p[1]=tf32r(v.y); p[2]=tf32r(v.z); p[3]=tf32r(v.w);
        }
        #pragma unroll
        for (int ii = 0; ii < 4; ii++){
            int i = tid + ii*256;
            int r = i >> 5, c = (i & 31) << 2;
            float4 v = *(const float4*)(W + (size_t)(kt + r)*1536 + nBase + c);
            float* p = Bs + r*136 + c;
            p[0]=tf32r(v.x); p[1]=tf32r(v.y); p[2]=tf32r(v.z); p[3]=tf32r(v.w);
        }
        __syncthreads();
        #pragma unroll
        for (int ks = 0; ks < 4; ks++){
            int kb = ks*8;
            unsigned a[4][4], bb[4][2];
            #pragma unroll
            for (int mt=0; mt<4; mt++){
                int r0 = wm*64 + mt*16;
                a[mt][0]=fu(As[(r0+gr   )*36 + kb+gc  ]);
                a[mt][1]=fu(As[(r0+gr+8 )*36 + kb+gc  ]);
                a[mt][2]=fu(As[(r0+gr   )*36 + kb+gc+4]);
                a[mt][3]=fu(As[(r0+gr+8 )*36 + kb+gc+4]);
            }
            #pragma unroll
            for (int nt=0; nt<4; nt++){
                int n0 = wn*32 + nt*8;
                bb[nt][0]=fu(Bs[(kb+gc  )*136 + n0+gr]);
                bb[nt][1]=fu(Bs[(kb+gc+4)*136 + n0+gr]);
            }
            #pragma unroll
            for (int mt=0; mt<4; mt++)
                #pragma unroll
                for (int nt=0; nt<4; nt++)
                    mma8(acc[mt][nt], a[mt], bb[nt]);
        }
        __syncthreads();
    }
    #pragma unroll
    for (int mt=0; mt<4; mt++){
        #pragma unroll
        for (int nt=0; nt<4; nt++){
            int row = mBase + wm*64 + mt*16 + gr;
            int col = nBase + wn*32 + nt*8 + 2*gc;
            int p   = col >> 9;
            int rem = col & 511;
            int h   = rem >> 6, d = rem & 63;
            float* dst = (p==0 ? g_Q : (p==1 ? g_K : g_V));
            #pragma unroll
            for (int rr=0; rr<2; rr++){
                int r = row + rr*8;
                int b = r >> 10, n = r & 1023;
                float2 v = make_float2(acc[mt][nt][rr*2], acc[mt][nt][rr*2+1]);
                *(float2*)(dst + ((size_t)((b*8+h)*1024 + n))*64 + d) = v;
            }
        }
    }
}

// ============================================================================
// Kernel 2: attention v3.  CTA = 256 q-rows, 8 warps x 32 rows (2 m-tiles).
// Q fragments + O accumulator register-resident. K/V fragments reused across
// 2 m-tiles (halves K/V smem bytes per row).  64-col j-chunks, 16 iterations.
// ============================================================================
#define PS  68    // P stride (== 4 mod 32); also Q staging
#define KSS 68    // K stride (== 4 mod 32)
#define VS  72    // V stride (== 8 mod 32)
#define ATT_SMEM ((256*PS + 64*KSS + 64*VS)*4)

__global__ __launch_bounds__(256, 1) void attn_kernel(const float* __restrict__ mask)
{
    extern __shared__ float sm[];
    float* Ps = sm;              // 256 x PS (Q staging, then P tiles)
    float* Ks = Ps + 256*PS;     //  64 x KSS
    float* Vs = Ks + 64*KSS;     //  64 x VS

    const int tid = threadIdx.x, lane = tid & 31, w = tid >> 5;
    const int gr = lane >> 2, gc = lane & 3;
    const int b = blockIdx.z, h = blockIdx.y, rt = blockIdx.x;
    const int r0 = w * 32;   // warp owns 32 q-rows (2 m-tiles of 16)

    const float* Qg = g_Q + ((size_t)((b*8+h)*1024 + rt*256))*64;
    const float* Kg = g_K + ((size_t)((b*8+h)*1024))*64;
    const float* Vg = g_V + ((size_t)((b*8+h)*1024))*64;
    const float* Mg = mask + ((size_t)(h*1024 + rt*256))*1024;

    // ---- stage Q (pre-scaled, tf32-rounded) through Ps, then lift to regs ----
    #pragma unroll
    for (int ii = 0; ii < 16; ii++){
        int i = tid + ii*256;
        int r = i >> 4, c = (i & 15) << 2;
        float4 v = *(const float4*)(Qg + r*64 + c);
        float* p = Ps + r*PS + c;
        p[0]=tf32r(v.x*SCALE); p[1]=tf32r(v.y*SCALE);
        p[2]=tf32r(v.z*SCALE); p[3]=tf32r(v.w*SCALE);
    }
    __syncthreads();

    unsigned q[2][8][4];
    #pragma unroll
    for (int mt = 0; mt < 2; mt++){
        int rr = r0 + mt*16;
        #pragma unroll
        for (int ks = 0; ks < 8; ks++){
            int kb = ks*8;
            q[mt][ks][0]=fu(Ps[(rr+gr  )*PS + kb+gc  ]);
            q[mt][ks][1]=fu(Ps[(rr+gr+8)*PS + kb+gc  ]);
            q[mt][ks][2]=fu(Ps[(rr+gr  )*PS + kb+gc+4]);
            q[mt][ks][3]=fu(Ps[(rr+gr+8)*PS + kb+gc+4]);
        }
    }
    // (no extra sync needed: first P write happens after the in-loop
    //  __syncthreads, by which time every warp has read its Q fragments)

    float o[2][8][4];
    #pragma unroll
    for (int mt=0; mt<2; mt++)
        #pragma unroll
        for (int nt=0; nt<8; nt++){
            o[mt][nt][0]=0.f; o[mt][nt][1]=0.f;
            o[mt][nt][2]=0.f; o[mt][nt][3]=0.f;
        }
    float mst[2][2] = {{-1e30f,-1e30f},{-1e30f,-1e30f}};
    float lst[2][2] = {{0.f,0.f},{0.f,0.f}};

    for (int jt = 0; jt < 16; jt++){
        const float* kp = Kg + jt*64*64;
        const float* vp = Vg + jt*64*64;
        // load K,V chunk: 64x64 each (1024 float4 each; 4/thread)
        #pragma unroll
        for (int ii = 0; ii < 4; ii++){
            int i = tid + ii*256;
            int r = i >> 4, c = (i & 15) << 2;
            float4 vk = *(const float4*)(kp + r*64 + c);
            float* p = Ks + r*KSS + c;
            p[0]=tf32r(vk.x); p[1]=tf32r(vk.y); p[2]=tf32r(vk.z); p[3]=tf32r(vk.w);
            float4 vv = *(const float4*)(vp + r*64 + c);
            float* qq = Vs + r*VS + c;
            qq[0]=tf32r(vv.x); qq[1]=tf32r(vv.y); qq[2]=tf32r(vv.z); qq[3]=tf32r(vv.w);
        }
        __syncthreads();

        // S = Q K^T : warp's 32 rows x 64 cols. K frag reused across 2 m-tiles.
        float s[2][8][4];
        #pragma unroll
        for (int mt=0; mt<2; mt++)
            #pragma unroll
            for (int i=0;i<8;i++){
                s[mt][i][0]=0.f; s[mt][i][1]=0.f;
                s[mt][i][2]=0.f; s[mt][i][3]=0.f;
            }
        #pragma unroll
        for (int ks=0; ks<8; ks++){
            int kb = ks*8;
            #pragma unroll
            for (int nt=0; nt<8; nt++){
                int n0 = nt*8;
                unsigned bb[2] = {
                    fu(Ks[(n0+gr)*KSS + kb+gc  ]),
                    fu(Ks[(n0+gr)*KSS + kb+gc+4]) };
                mma8(s[0][nt], q[0][ks], bb);
                mma8(s[1][nt], q[1][ks], bb);
            }
        }

        // online softmax per m-tile (scale already folded into Q)
        #pragma unroll
        for (int mt=0; mt<2; mt++){
            float ml0 = -1e30f, ml1 = -1e30f;
            #pragma unroll
            for (int nt=0; nt<8; nt++){
                ml0 = fmaxf(ml0, fmaxf(s[mt][nt][0], s[mt][nt][1]));
                ml1 = fmaxf(ml1, fmaxf(s[mt][nt][2], s[mt][nt][3]));
            }
            ml0 = fmaxf(ml0, __shfl_xor_sync(0xffffffffu, ml0, 1));
            ml0 = fmaxf(ml0, __shfl_xor_sync(0xffffffffu, ml0, 2));
            ml1 = fmaxf(ml1, __shfl_xor_sync(0xffffffffu, ml1, 1));
            ml1 = fmaxf(ml1, __shfl_xor_sync(0xffffffffu, ml1, 2));
            float mn0 = fmaxf(mst[mt][0], ml0), mn1 = fmaxf(mst[mt][1], ml1);
            float al0 = __expf(mst[mt][0] - mn0), al1 = __expf(mst[mt][1] - mn1);
            mst[mt][0] = mn0; mst[mt][1] = mn1;

            float ls0 = 0.f, ls1 = 0.f;
            const float* mrp0 = Mg + (size_t)(r0+mt*16+gr)*1024 + jt*64;
            const float* mrp1 = mrp0 + 8*1024;
            #pragma unroll
            for (int nt=0; nt<8; nt++){
                int cc = nt*8 + 2*gc;
                float e0 = __expf(s[mt][nt][0]-mn0), e1 = __expf(s[mt][nt][1]-mn0);
                float e2 = __expf(s[mt][nt][2]-mn1), e3 = __expf(s[mt][nt][3]-mn1);
                ls0 += e0 + e1; ls1 += e2 + e3;
                float2 mk0 = *(const float2*)(mrp0 + cc);
                float2 mk1 = *(const float2*)(mrp1 + cc);
                *(float2*)(Ps + (r0+mt*16+gr  )*PS + cc) =
                    make_float2(tf32r(e0*mk0.x), tf32r(e1*mk0.y));
                *(float2*)(Ps + (r0+mt*16+gr+8)*PS + cc) =
                    make_float2(tf32r(e2*mk1.x), tf32r(e3*mk1.y));
            }
            lst[mt][0] = lst[mt][0]*al0 + ls0;
            lst[mt][1] = lst[mt][1]*al1 + ls1;
            #pragma unroll
            for (int nt=0; nt<8; nt++){
                o[mt][nt][0]*=al0; o[mt][nt][1]*=al0;
                o[mt][nt][2]*=al1; o[mt][nt][3]*=al1;
            }
        }
        __syncwarp();   // Ps rows are warp-private

        // O += P @ V : warp's 32 rows x 64 d-cols, k = 64. V frag reused 2x.
        #pragma unroll
        for (int ks=0; ks<8; ks++){
            int kb = ks*8;
            unsigned p0[4] = {
                fu(Ps[(r0+gr   )*PS + kb+gc  ]),
                fu(Ps[(r0+gr+8 )*PS + kb+gc  ]),
                fu(Ps[(r0+gr   )*PS + kb+gc+4]),
                fu(Ps[(r0+gr+8 )*PS + kb+gc+4]) };
            unsigned p1[4] = {
                fu(Ps[(r0+16+gr  )*PS + kb+gc  ]),
                fu(Ps[(r0+16+gr+8)*PS + kb+gc  ]),
                fu(Ps[(r0+16+gr  )*PS + kb+gc+4]),
                fu(Ps[(r0+16+gr+8)*PS + kb+gc+4]) };
            #pragma unroll
            for (int nt=0; nt<8; nt++){
                int n0 = nt*8;
                unsigned bb[2] = {
                    fu(Vs[(kb+gc  )*VS + n0+gr]),
                    fu(Vs[(kb+gc+4)*VS + n0+gr]) };
                mma8(o[0][nt], p0, bb);
                mma8(o[1][nt], p1, bb);
            }
        }
        __syncthreads();   // before next iteration overwrites Ks/Vs
    }

    // finalize: reduce l across the 4 lanes per row, divide, store
    float* Og = g_O + ((size_t)(b*1024 + rt*256))*512 + h*64;
    #pragma unroll
    for (int mt=0; mt<2; mt++){
        float l0 = lst[mt][0], l1 = lst[mt][1];
        l0 += __shfl_xor_sync(0xffffffffu, l0, 1);
        l0 += __shfl_xor_sync(0xffffffffu, l0, 2);
        l1 += __shfl_xor_sync(0xffffffffu, l1, 1);
        l1 += __shfl_xor_sync(0xffffffffu, l1, 2);
        float inv0 = 1.f / l0, inv1 = 1.f / l1;
        #pragma unroll
        for (int nt=0; nt<8; nt++){
            int d = nt*8 + 2*gc;
            *(float2*)(Og + (size_t)(r0+mt*16+gr  )*512 + d) =
                make_float2(o[mt][nt][0]*inv0, o[mt][nt][1]*inv0);
            *(float2*)(Og + (size_t)(r0+mt*16+gr+8)*512 + d) =
                make_float2(o[mt][nt][2]*inv1, o[mt][nt][3]*inv1);
        }
    }
}

// ============================================================================
// Kernel 3: out = g_O[32768,512] @ W_out[512,512] + b_out  (unchanged)
// ============================================================================
__global__ __launch_bounds__(256) void out_gemm_kernel(
    const float* __restrict__ W, const float* __restrict__ bias,
    float* __restrict__ out)
{
    __shared__ float As[128*36];
    __shared__ float Bs[32*136];
    const int tid = threadIdx.x, lane = tid & 31, w = tid >> 5;
    const int gr = lane >> 2, gc = lane & 3;
    const int wm = w & 1, wn = w >> 1;
    const int mBase = blockIdx.y * 128, nBase = blockIdx.x * 128;

    float acc[4][4][4];
    #pragma unroll
    for (int i=0;i<4;i++)
        #pragma unroll
        for (int j=0;j<4;j++)
            #pragma unroll
            for (int c=0;c<4;c++) acc[i][j][c] = 0.f;

    for (int kt = 0; kt < 512; kt += 32){
        #pragma unroll
        for (int ii = 0; ii < 4; ii++){
            int i = tid + ii*256;
            int r = i >> 3, c = (i & 7) << 2;
            float4 v = *(const float4*)(g_O + (size_t)(mBase + r)*512 + kt + c);
            float* p = As + r*36 + c;
            p[0]=tf32r(v.x); p[1]=tf32r(v.y); p[2]=tf32r(v.z); p[3]=tf32r(v.w);
        }
        #pragma unroll
        for (int ii = 0; ii < 4; ii++){
            int i = tid + ii*256;
            int r = i >> 5, c = (i & 31) << 2;
            float4 v = *(const float4*)(W + (size_t)(kt + r)*512 + nBase + c);
            float* p = Bs + r*136 + c;
            p[0]=tf32r(v.x); p[1]=tf32r(v.y); p[2]=tf32r(v.z); p[3]=tf32r(v.w);
        }
        __syncthreads();
        #pragma unroll
        for (int ks = 0; ks < 4; ks++){
            int kb = ks*8;
            unsigned a[4][4], bb[4][2];
            #pragma unroll
            for (int mt=0; mt<4; mt++){
                int r0 = wm*64 + mt*16;
                a[mt][0]=fu(As[(r0+gr   )*36 + kb+gc  ]);
                a[mt][1]=fu(As[(r0+gr+8 )*36 + kb+gc  ]);
                a[mt][2]=fu(As[(r0+gr   )*36 + kb+gc+4]);
                a[mt][3]=fu(As[(r0+gr+8 )*36 + kb+gc+4]);
            }
            #pragma unroll
            for (int nt=0; nt<4; nt++){
                int n0 = wn*32 + nt*8;
                bb[nt][0]=fu(Bs[(kb+gc  )*136 + n0+gr]);
                bb[nt][1]=fu(Bs[(kb+gc+4)*136 + n0+gr]);
            }
            #pragma unroll
            for (int mt=0; mt<4; mt++)
                #pragma unroll
                for (int nt=0; nt<4; nt++)
                    mma8(acc[mt][nt], a[mt], bb[nt]);
        }
        __syncthreads();
    }
    #pragma unroll
    for (int mt=0; mt<4; mt++){
        #pragma unroll
        for (int nt=0; nt<4; nt++){
            int row = mBase + wm*64 + mt*16 + gr;
            int col = nBase + wn*32 + nt*8 + 2*gc;
            float b0 = bias[col], b1 = bias[col+1];
            *(float2*)(out + (size_t)row*512 + col) =
                make_float2(acc[mt][nt][0] + b0, acc[mt][nt][1] + b1);
            *(float2*)(out + (size_t)(row+8)*512 + col) =
                make_float2(acc[mt][nt][2] + b0, acc[mt][nt][3] + b1);
        }
    }
}

// ============================================================================
extern "C" void kernel_launch(void* const* d_in, const int* in_sizes, int n_in,
                              void* d_out, int out_size)
{
    (void)in_sizes; (void)n_in; (void)out_size;
    const float* x    = (const float*)d_in[0];
    const float* Wqkv = (const float*)d_in[1];
    const float* Wout = (const float*)d_in[2];
    const float* bout = (const float*)d_in[3];
    const float* mask = (const float*)d_in[4];
    float* out = (float*)d_out;

    cudaFuncSetAttribute(attn_kernel,
                         cudaFuncAttributeMaxDynamicSharedMemorySize, ATT_SMEM);

    qkv_gemm_kernel<<<dim3(12, 256), 256>>>(x, Wqkv);
    attn_kernel<<<dim3(4, 8, 32), 256, ATT_SMEM>>>(mask);
    out_gemm_kernel<<<dim3(4, 256), 256>>>(Wout, bout, out);
}

// round 9
// speedup vs baseline: 1.1328x; 1.1328x over previous
#include <cuda_runtime.h>
#include <cstdint>
#include <cstddef>

#define Bb 32
#define Nn 1024
#define DIM 512
#define Hh 8
#define DHd 64
#define SCALE 0.125f

// Scratch (device globals: allocation-free per harness rules)
__device__ float g_Q[Bb*Hh*Nn*DHd];   // [b,h,n,d]
__device__ float g_K[Bb*Hh*Nn*DHd];
__device__ float g_V[Bb*Hh*Nn*DHd];
__device__ float g_O[Bb*Nn*Hh*DHd];   // [b,n,h*64+d]

__device__ __forceinline__ float tf32r(float x){
    unsigned r; asm("cvt.rna.tf32.f32 %0, %1;" : "=r"(r) : "f"(x));
    return __uint_as_float(r);
}
__device__ __forceinline__ unsigned fu(float x){ return __float_as_uint(x); }

// D += A(16x8,row) * B(8x8,col)  tf32
__device__ __forceinline__ void mma8(float* d, const unsigned* a, const unsigned* b){
    asm volatile(
        "mma.sync.aligned.m16n8k8.row.col.f32.tf32.tf32.f32 "
        "{%0,%1,%2,%3},{%4,%5,%6,%7},{%8,%9},{%0,%1,%2,%3};\n"
        : "+f"(d[0]), "+f"(d[1]), "+f"(d[2]), "+f"(d[3])
        : "r"(a[0]), "r"(a[1]), "r"(a[2]), "r"(a[3]), "r"(b[0]), "r"(b[1]));
}

// ============================================================================
// GEMM v2: block 256m x 128n, 8 warps (4m x 2n), warp tile 64x64.
// Double-buffered smem + register-held prefetch, ONE __syncthreads per ktile.
// MODE 0: C = x @ W_qkv, scatter to g_Q/g_K/g_V.   (LDB=1536)
// MODE 1: C = g_O @ W_out + bias -> out.           (LDB=512)
// ============================================================================
#define GEMM_SMEM ((2*256*36 + 2*32*136)*4)   // 108,544 B

template<int LDB, int MODE>
__global__ __launch_bounds__(256, 1) void gemm256(
    const float* __restrict__ Ain, const float* __restrict__ W,
    const float* __restrict__ bias, float* __restrict__ outp)
{
    extern __shared__ float smem[];
    float* As0 = smem;
    float* As1 = smem + 256*36;
    float* Bs0 = smem + 2*256*36;
    float* Bs1 = smem + 2*256*36 + 32*136;

    const int tid = threadIdx.x, lane = tid & 31, w = tid >> 5;
    const int gr = lane >> 2, gc = lane & 3;
    const int wm = w >> 1, wn = w & 1;              // 4 x 2 warps
    const int mBase = blockIdx.y * 256, nBase = blockIdx.x * 128;

    const float* A = (MODE == 0) ? Ain : g_O;

    float acc[4][8][4];
    #pragma unroll
    for (int i=0;i<4;i++)
        #pragma unroll
        for (int j=0;j<8;j++)
            #pragma unroll
            for (int c=0;c<4;c++) acc[i][j][c] = 0.f;

    // per-thread staging coordinates
    float4 ar[8], br[4];
    const int arr[8] = { (tid+0*256)>>3, (tid+1*256)>>3, (tid+2*256)>>3, (tid+3*256)>>3,
                         (tid+4*256)>>3, (tid+5*256)>>3, (tid+6*256)>>3, (tid+7*256)>>3 };
    const int arc = (tid & 7) << 2;
    const int brr[4] = { (tid+0*256)>>5, (tid+1*256)>>5, (tid+2*256)>>5, (tid+3*256)>>5 };
    const int brc = (tid & 31) << 2;

    // preload ktile 0
    {
        const float* Ag = A + (size_t)mBase * 512;
        #pragma unroll
        for (int ii = 0; ii < 8; ii++)
            ar[ii] = *(const float4*)(Ag + (size_t)arr[ii]*512 + arc);
        const float* Wg = W + nBase;
        #pragma unroll
        for (int ii = 0; ii < 4; ii++)
            br[ii] = *(const float4*)(Wg + (size_t)brr[ii]*LDB + brc);
    }

    for (int kt = 0; kt < 16; kt++){
        float* Asb = (kt & 1) ? As1 : As0;
        float* Bsb = (kt & 1) ? Bs1 : Bs0;

        // STS current tile (tf32-rounded)
        #pragma unroll
        for (int ii = 0; ii < 8; ii++){
            float* p = Asb + arr[ii]*36 + arc;
            p[0]=tf32r(ar[ii].x); p[1]=tf32r(ar[ii].y);
            p[2]=tf32r(ar[ii].z); p[3]=tf32r(ar[ii].w);
        }
        #pragma unroll
        for (int ii = 0; ii < 4; ii++){
            float* p = Bsb + brr[ii]*136 + brc;
            p[0]=tf32r(br[ii].x); p[1]=tf32r(br[ii].y);
            p[2]=tf32r(br[ii].z); p[3]=tf32r(br[ii].w);
        }
        __syncthreads();

        // issue next tile's LDGs (hidden under compute)
        if (kt < 15){
            const float* Ag = A + (size_t)mBase * 512 + (kt+1)*32;
            #pragma unroll
            for (int ii = 0; ii < 8; ii++)
                ar[ii] = *(const float4*)(Ag + (size_t)arr[ii]*512 + arc);
            const float* Wg = W + (size_t)(kt+1)*32*LDB + nBase;
            #pragma unroll
            for (int ii = 0; ii < 4; ii++)
                br[ii] = *(const float4*)(Wg + (size_t)brr[ii]*LDB + brc);
        }

        // compute: 4 k-slices x (4 m-tiles x 8 n-tiles)
        #pragma unroll
        for (int ks = 0; ks < 4; ks++){
            int kb = ks*8;
            unsigned afr[4][4], bfr[8][2];
            #pragma unroll
            for (int mt=0; mt<4; mt++){
                int rr = wm*64 + mt*16;
                afr[mt][0]=fu(Asb[(rr+gr  )*36 + kb+gc  ]);
                afr[mt][1]=fu(Asb[(rr+gr+8)*36 + kb+gc  ]);
                afr[mt][2]=fu(Asb[(rr+gr  )*36 + kb+gc+4]);
                afr[mt][3]=fu(Asb[(rr+gr+8)*36 + kb+gc+4]);
            }
            #pragma unroll
            for (int nt=0; nt<8; nt++){
                int n0 = wn*64 + nt*8;
                bfr[nt][0]=fu(Bsb[(kb+gc  )*136 + n0+gr]);
                bfr[nt][1]=fu(Bsb[(kb+gc+4)*136 + n0+gr]);
            }
            #pragma unroll
            for (int mt=0; mt<4; mt++)
                #pragma unroll
                for (int nt=0; nt<8; nt++)
                    mma8(acc[mt][nt], afr[mt], bfr[nt]);
        }
        // no trailing sync needed: next STS targets the other buffer, and the
        // one sync per iter orders buffer reuse two iterations apart.
    }

    // epilogue
    #pragma unroll
    for (int mt=0; mt<4; mt++){
        #pragma unroll
        for (int nt=0; nt<8; nt++){
            int row = mBase + wm*64 + mt*16 + gr;
            int col = nBase + wn*64 + nt*8 + 2*gc;
            if (MODE == 0){
                int p = col >> 9, h = (col >> 6) & 7, d = col & 63;
                float* dst = (p==0 ? g_Q : (p==1 ? g_K : g_V));
                #pragma unroll
                for (int rr=0; rr<2; rr++){
                    int r = row + rr*8;
                    int b = r >> 10, n = r & 1023;
                    *(float2*)(dst + ((size_t)((b*8+h)*1024 + n))*64 + d) =
                        make_float2(acc[mt][nt][rr*2], acc[mt][nt][rr*2+1]);
                }
            } else {
                float b0 = bias[col], b1 = bias[col+1];
                *(float2*)(outp + (size_t)row*512 + col) =
                    make_float2(acc[mt][nt][0] + b0, acc[mt][nt][1] + b1);
                *(float2*)(outp + (size_t)(row+8)*512 + col) =
                    make_float2(acc[mt][nt][2] + b0, acc[mt][nt][3] + b1);
            }
        }
    }
}

// ============================================================================
// Kernel 2: attention (exact R4 version — best known: ~690us).
// One block per (b, h, 128-row tile). 256 threads. 64-col j-chunks.
// Smem 103KB -> 2 CTAs/SM, single wave of 256 CTAs.
// ============================================================================
#define QS 68     // Q/K smem stride (== 4 mod 32)
#define VS 72     // V smem stride (== 8 mod 32)
#define PS 68     // P smem stride (== 4 mod 32)
#define ATT_SMEM ((128*QS + 64*QS + 64*VS + 128*PS)*4)

__global__ __launch_bounds__(256, 2) void attn_kernel(const float* __restrict__ mask)
{
    extern __shared__ float sm[];
    float* Qs = sm;                 // 128 x 64 (stride QS)
    float* Ks = Qs + 128*QS;        //  64 x 64 (stride QS)
    float* Vs = Ks + 64*QS;         //  64 x 64 (stride VS)
    float* Ps = Vs + 64*VS;         // 128 x 64 (stride PS)

    const int tid = threadIdx.x, lane = tid & 31, w = tid >> 5;
    const int gr = lane >> 2, gc = lane & 3;
    const int b = blockIdx.z, h = blockIdx.y, rt = blockIdx.x;
    const int r0 = w * 16;   // each warp owns 16 q-rows

    const float* Qg = g_Q + ((size_t)((b*8+h)*1024 + rt*128))*64;
    const float* Kg = g_K + ((size_t)((b*8+h)*1024))*64;
    const float* Vg = g_V + ((size_t)((b*8+h)*1024))*64;
    const float* Mg = mask + ((size_t)(h*1024 + rt*128))*1024;

    // Q tile: 128 x 64, tf32-rounded
    #pragma unroll
    for (int ii = 0; ii < 8; ii++){
        int i = tid + ii*256;
        int r = i >> 4, c = (i & 15) << 2;
        float4 v = *(const float4*)(Qg + r*64 + c);
        float* p = Qs + r*QS + c;
        p[0]=tf32r(v.x); p[1]=tf32r(v.y); p[2]=tf32r(v.z); p[3]=tf32r(v.w);
    }

    float o[8][4];
    #pragma unroll
    for (int i=0;i<8;i++){ o[i][0]=0.f;o[i][1]=0.f;o[i][2]=0.f;o[i][3]=0.f; }
    float mrow0 = -1e30f, mrow1 = -1e30f, lrow0 = 0.f, lrow1 = 0.f;

    for (int jt = 0; jt < 16; jt++){       // 64-col chunks
        const float* kp = Kg + jt*64*64;
        const float* vp = Vg + jt*64*64;
        #pragma unroll
        for (int ii = 0; ii < 4; ii++){
            int i = tid + ii*256;
            int r = i >> 4, c = (i & 15) << 2;
            float4 vk = *(const float4*)(kp + r*64 + c);
            float* p = Ks + r*QS + c;
            p[0]=tf32r(vk.x); p[1]=tf32r(vk.y); p[2]=tf32r(vk.z); p[3]=tf32r(vk.w);
            float4 vv = *(const float4*)(vp + r*64 + c);
            float* q = Vs + r*VS + c;
            q[0]=tf32r(vv.x); q[1]=tf32r(vv.y); q[2]=tf32r(vv.z); q[3]=tf32r(vv.w);
        }
        __syncthreads();

        // S = Q K^T : warp's 16 rows x 64 cols
        float s[8][4];
        #pragma unroll
        for (int i=0;i<8;i++){ s[i][0]=0.f;s[i][1]=0.f;s[i][2]=0.f;s[i][3]=0.f; }
        #pragma unroll
        for (int ks=0; ks<8; ks++){
            int kb = ks*8;
            unsigned a[4] = {
                fu(Qs[(r0+gr  )*QS + kb+gc  ]),
                fu(Qs[(r0+gr+8)*QS + kb+gc  ]),
                fu(Qs[(r0+gr  )*QS + kb+gc+4]),
                fu(Qs[(r0+gr+8)*QS + kb+gc+4]) };
            #pragma unroll
            for (int nt=0; nt<8; nt++){
                int n0 = nt*8;
                unsigned bb[2] = {
                    fu(Ks[(n0+gr)*QS + kb+gc  ]),
                    fu(Ks[(n0+gr)*QS + kb+gc+4]) };
                mma8(s[nt], a, bb);
            }
        }

        // scale + online softmax state
        float ml0 = -1e30f, ml1 = -1e30f;
        #pragma unroll
        for (int nt=0; nt<8; nt++){
            s[nt][0]*=SCALE; s[nt][1]*=SCALE; s[nt][2]*=SCALE; s[nt][3]*=SCALE;
            ml0 = fmaxf(ml0, fmaxf(s[nt][0], s[nt][1]));
            ml1 = fmaxf(ml1, fmaxf(s[nt][2], s[nt][3]));
        }
        ml0 = fmaxf(ml0, __shfl_xor_sync(0xffffffffu, ml0, 1));
        ml0 = fmaxf(ml0, __shfl_xor_sync(0xffffffffu, ml0, 2));
        ml1 = fmaxf(ml1, __shfl_xor_sync(0xffffffffu, ml1, 1));
        ml1 = fmaxf(ml1, __shfl_xor_sync(0xffffffffu, ml1, 2));
        float mn0 = fmaxf(mrow0, ml0), mn1 = fmaxf(mrow1, ml1);
        float al0 = __expf(mrow0 - mn0), al1 = __expf(mrow1 - mn1);
        mrow0 = mn0; mrow1 = mn1;

        float ls0 = 0.f, ls1 = 0.f;
        const float* mrp0 = Mg + (size_t)(r0+gr  )*1024 + jt*64;
        const float* mrp1 = Mg + (size_t)(r0+gr+8)*1024 + jt*64;
        #pragma unroll
        for (int nt=0; nt<8; nt++){
            int cc = nt*8 + 2*gc;
            float e0 = __expf(s[nt][0]-mn0), e1 = __expf(s[nt][1]-mn0);
            float e2 = __expf(s[nt][2]-mn1), e3 = __expf(s[nt][3]-mn1);
            ls0 += e0 + e1; ls1 += e2 + e3;
            float2 mk0 = *(const float2*)(mrp0 + cc);
            float2 mk1 = *(const float2*)(mrp1 + cc);
            *(float2*)(Ps + (r0+gr  )*PS + cc) =
                make_float2(tf32r(e0*mk0.x), tf32r(e1*mk0.y));
            *(float2*)(Ps + (r0+gr+8)*PS + cc) =
                make_float2(tf32r(e2*mk1.x), tf32r(e3*mk1.y));
        }
        lrow0 = lrow0*al0 + ls0;
        lrow1 = lrow1*al1 + ls1;
        #pragma unroll
        for (int nt=0; nt<8; nt++){
            o[nt][0]*=al0; o[nt][1]*=al0; o[nt][2]*=al1; o[nt][3]*=al1;
        }
        __syncwarp();   // Ps rows are warp-private

        // O += P @ V : warp's 16 rows x 64 d-cols, k = 64
        #pragma unroll
        for (int ks=0; ks<8; ks++){
            int kb = ks*8;
            unsigned a[4] = {
                fu(Ps[(r0+gr  )*PS + kb+gc  ]),
                fu(Ps[(r0+gr+8)*PS + kb+gc  ]),
                fu(Ps[(r0+gr  )*PS + kb+gc+4]),
                fu(Ps[(r0+gr+8)*PS + kb+gc+4]) };
            #pragma unroll
            for (int nt=0; nt<8; nt++){
                int n0 = nt*8;
                unsigned bb[2] = {
                    fu(Vs[(kb+gc  )*VS + n0+gr]),
                    fu(Vs[(kb+gc+4)*VS + n0+gr]) };
                mma8(o[nt], a, bb);
            }
        }
        __syncthreads();   // before next iteration overwrites Ks/Vs
    }

    // finalize
    lrow0 += __shfl_xor_sync(0xffffffffu, lrow0, 1);
    lrow0 += __shfl_xor_sync(0xffffffffu, lrow0, 2);
    lrow1 += __shfl_xor_sync(0xffffffffu, lrow1, 1);
    lrow1 += __shfl_xor_sync(0xffffffffu, lrow1, 2);
    float inv0 = 1.f / lrow0, inv1 = 1.f / lrow1;

    float* Og = g_O + ((size_t)(b*1024 + rt*128))*512 + h*64;
    #pragma unroll
    for (int nt=0; nt<8; nt++){
        int d = nt*8 + 2*gc;
        *(float2*)(Og + (size_t)(r0+gr  )*512 + d) =
            make_float2(o[nt][0]*inv0, o[nt][1]*inv0);
        *(float2*)(Og + (size_t)(r0+gr+8)*512 + d) =
            make_float2(o[nt][2]*inv1, o[nt][3]*inv1);
    }
}

// ============================================================================
extern "C" void kernel_launch(void* const* d_in, const int* in_sizes, int n_in,
                              void* d_out, int out_size)
{
    (void)in_sizes; (void)n_in; (void)out_size;
    const float* x    = (const float*)d_in[0];
    const float* Wqkv = (const float*)d_in[1];
    const float* Wout = (const float*)d_in[2];
    const float* bout = (const float*)d_in[3];
    const float* mask = (const float*)d_in[4];
    float* out = (float*)d_out;

    cudaFuncSetAttribute(gemm256<1536,0>,
                         cudaFuncAttributeMaxDynamicSharedMemorySize, GEMM_SMEM);
    cudaFuncSetAttribute(gemm256<512,1>,
                         cudaFuncAttributeMaxDynamicSharedMemorySize, GEMM_SMEM);
    cudaFuncSetAttribute(attn_kernel,
                         cudaFuncAttributeMaxDynamicSharedMemorySize, ATT_SMEM);

    gemm256<1536,0><<<dim3(12, 128), 256, GEMM_SMEM>>>(x, Wqkv, nullptr, nullptr);
    attn_kernel<<<dim3(8, 8, 32), 256, ATT_SMEM>>>(mask);
    gemm256<512,1><<<dim3(4, 128), 256, GEMM_SMEM>>>(nullptr, Wout, bout, out);
}

// round 14
// speedup vs baseline: 1.2202x; 1.0771x over previous
#include <cuda_runtime.h>
#include <cstdint>
#include <cstddef>

#define Bb 32
#define Nn 1024
#define DIM 512
#define Hh 8
#define DHd 64
#define SCALE 0.125f

// Scratch (device globals: allocation-free per harness rules)
__device__ float g_Q[Bb*Hh*Nn*DHd];   // [b,h,n,d]  (tf32-rounded, pre-scaled)
__device__ float g_K[Bb*Hh*Nn*DHd];   // tf32-rounded
__device__ float g_V[Bb*Hh*Nn*DHd];   // tf32-rounded
__device__ float g_O[Bb*Nn*Hh*DHd];   // [b,n,h*64+d]

__device__ __forceinline__ float tf32r(float x){
    unsigned r; asm("cvt.rna.tf32.f32 %0, %1;" : "=r"(r) : "f"(x));
    return __uint_as_float(r);
}
__device__ __forceinline__ unsigned fu(float x){ return __float_as_uint(x); }
__device__ __forceinline__ uint32_t smem_u32(const void* p){
    uint32_t a;
    asm("{ .reg .u64 t; cvta.to.shared.u64 t, %1; cvt.u32.u64 %0, t; }"
        : "=r"(a) : "l"(p));
    return a;
}
#define CP_ASYNC16(dst, src) \
    asm volatile("cp.async.cg.shared.global [%0], [%1], 16;" \
                 :: "r"(dst), "l"(src) : "memory")
#define CP_COMMIT() asm volatile("cp.async.commit_group;" ::: "memory")
#define CP_WAIT0()  asm volatile("cp.async.wait_group 0;" ::: "memory")

// D += A(16x8,row) * B(8x8,col)  tf32
__device__ __forceinline__ void mma8(float* d, const unsigned* a, const unsigned* b){
    asm volatile(
        "mma.sync.aligned.m16n8k8.row.col.f32.tf32.tf32.f32 "
        "{%0,%1,%2,%3},{%4,%5,%6,%7},{%8,%9},{%0,%1,%2,%3};\n"
        : "+f"(d[0]), "+f"(d[1]), "+f"(d[2]), "+f"(d[3])
        : "r"(a[0]), "r"(a[1]), "r"(a[2]), "r"(a[3]), "r"(b[0]), "r"(b[1]));
}

// ============================================================================
// GEMM: block 256m x 128n, 8 warps (4m x 2n), warp tile 64x64. (R9, 347us)
// MODE 0: C = x @ W_qkv -> g_Q/g_K/g_V, tf32-rounded (Q pre-scaled by 2^-3).
// MODE 1: C = g_O @ W_out + bias -> out.
// ============================================================================
#define GEMM_SMEM ((2*256*36 + 2*32*136)*4)   // 108,544 B

template<int LDB, int MODE>
__global__ __launch_bounds__(256, 1) void gemm256(
    const float* __restrict__ Ain, const float* __restrict__ W,
    const float* __restrict__ bias, float* __restrict__ outp)
{
    extern __shared__ float smem[];
    float* As0 = smem;
    float* As1 = smem + 256*36;
    float* Bs0 = smem + 2*256*36;
    float* Bs1 = smem + 2*256*36 + 32*136;

    const int tid = threadIdx.x, lane = tid & 31, w = tid >> 5;
    const int gr = lane >> 2, gc = lane & 3;
    const int wm = w >> 1, wn = w & 1;
    const int mBase = blockIdx.y * 256, nBase = blockIdx.x * 128;

    const float* A = (MODE == 0) ? Ain : g_O;

    float acc[4][8][4];
    #pragma unroll
    for (int i=0;i<4;i++)
        #pragma unroll
        for (int j=0;j<8;j++)
            #pragma unroll
            for (int c=0;c<4;c++) acc[i][j][c] = 0.f;

    float4 ar[8], br[4];
    const int arr[8] = { (tid+0*256)>>3, (tid+1*256)>>3, (tid+2*256)>>3, (tid+3*256)>>3,
                         (tid+4*256)>>3, (tid+5*256)>>3, (tid+6*256)>>3, (tid+7*256)>>3 };
    const int arc = (tid & 7) << 2;
    const int brr[4] = { (tid+0*256)>>5, (tid+1*256)>>5, (tid+2*256)>>5, (tid+3*256)>>5 };
    const int brc = (tid & 31) << 2;

    {
        const float* Ag = A + (size_t)mBase * 512;
        #pragma unroll
        for (int ii = 0; ii < 8; ii++)
            ar[ii] = *(const float4*)(Ag + (size_t)arr[ii]*512 + arc);
        const float* Wg = W + nBase;
        #pragma unroll
        for (int ii = 0; ii < 4; ii++)
            br[ii] = *(const float4*)(Wg + (size_t)brr[ii]*LDB + brc);
    }

    for (int kt = 0; kt < 16; kt++){
        float* Asb = (kt & 1) ? As1 : As0;
        float* Bsb = (kt & 1) ? Bs1 : Bs0;

        #pragma unroll
        for (int ii = 0; ii < 8; ii++){
            float* p = Asb + arr[ii]*36 + arc;
            p[0]=tf32r(ar[ii].x); p[1]=tf32r(ar[ii].y);
            p[2]=tf32r(ar[ii].z); p[3]=tf32r(ar[ii].w);
        }
        #pragma unroll
        for (int ii = 0; ii < 4; ii++){
            float* p = Bsb + brr[ii]*136 + brc;
            p[0]=tf32r(br[ii].x); p[1]=tf32r(br[ii].y);
            p[2]=tf32r(br[ii].z); p[3]=tf32r(br[ii].w);
        }
        __syncthreads();

        if (kt < 15){
            const float* Ag = A + (size_t)mBase * 512 + (kt+1)*32;
            #pragma unroll
            for (int ii = 0; ii < 8; ii++)
                ar[ii] = *(const float4*)(Ag + (size_t)arr[ii]*512 + arc);
            const float* Wg = W + (size_t)(kt+1)*32*LDB + nBase;
            #pragma unroll
            for (int ii = 0; ii < 4; ii++)
                br[ii] = *(const float4*)(Wg + (size_t)brr[ii]*LDB + brc);
        }

        #pragma unroll
        for (int ks = 0; ks < 4; ks++){
            int kb = ks*8;
            unsigned afr[4][4], bfr[8][2];
            #pragma unroll
            for (int mt=0; mt<4; mt++){
                int rr = wm*64 + mt*16;
                afr[mt][0]=fu(Asb[(rr+gr  )*36 + kb+gc  ]);
                afr[mt][1]=fu(Asb[(rr+gr+8)*36 + kb+gc  ]);
                afr[mt][2]=fu(Asb[(rr+gr  )*36 + kb+gc+4]);
                afr[mt][3]=fu(Asb[(rr+gr+8)*36 + kb+gc+4]);
            }
            #pragma unroll
            for (int nt=0; nt<8; nt++){
                int n0 = wn*64 + nt*8;
                bfr[nt][0]=fu(Bsb[(kb+gc  )*136 + n0+gr]);
                bfr[nt][1]=fu(Bsb[(kb+gc+4)*136 + n0+gr]);
            }
            #pragma unroll
            for (int mt=0; mt<4; mt++)
                #pragma unroll
                for (int nt=0; nt<8; nt++)
                    mma8(acc[mt][nt], afr[mt], bfr[nt]);
        }
    }

    #pragma unroll
    for (int mt=0; mt<4; mt++){
        #pragma unroll
        for (int nt=0; nt<8; nt++){
            int row = mBase + wm*64 + mt*16 + gr;
            int col = nBase + wn*64 + nt*8 + 2*gc;
            if (MODE == 0){
                int p = col >> 9, h = (col >> 6) & 7, d = col & 63;
                float* dst = (p==0 ? g_Q : (p==1 ? g_K : g_V));
                float sc = (p==0) ? SCALE : 1.0f;
                #pragma unroll
                for (int rr=0; rr<2; rr++){
                    int r = row + rr*8;
                    int b = r >> 10, n = r & 1023;
                    *(float2*)(dst + ((size_t)((b*8+h)*1024 + n))*64 + d) =
                        make_float2(tf32r(acc[mt][nt][rr*2]   * sc),
                                    tf32r(acc[mt][nt][rr*2+1] * sc));
                }
            } else {
                float b0 = bias[col], b1 = bias[col+1];
                *(float2*)(outp + (size_t)row*512 + col) =
                    make_float2(acc[mt][nt][0] + b0, acc[mt][nt][1] + b1);
                *(float2*)(outp + (size_t)(row+8)*512 + col) =
                    make_float2(acc[mt][nt][2] + b0, acc[mt][nt][3] + b1);
            }
        }
    }
}

// ============================================================================
// Attention v4: 8 warps x 16 rows, 64-col j-chunks.
// Q fragments register-resident; K/V double-buffered via cp.async (data
// pre-rounded to tf32 by the QKV epilogue, Q pre-scaled); ONE barrier per jt.
// smem = 106,496 B -> 2 CTAs/SM.
// ============================================================================
#define QS 68     // K smem stride (== 4 mod 32); also Ps/Q staging stride
#define VS 72     // V smem stride (== 8 mod 32)
#define PS 68
#define KVBUF (64*QS + 64*VS)
#define ATT_SMEM ((128*PS + 2*KVBUF)*4)

__global__ __launch_bounds__(256, 2) void attn_kernel(const float* __restrict__ mask)
{
    extern __shared__ float sm[];
    float* Ps  = sm;                      // 128 x PS (Q staging, then P)
    float* KV0 = sm + 128*PS;             // buf0: K 64xQS, V 64xVS
    float* KV1 = KV0 + KVBUF;             // buf1

    const int tid = threadIdx.x, lane = tid & 31, w = tid >> 5;
    const int gr = lane >> 2, gc = lane & 3;
    const int b = blockIdx.z, h = blockIdx.y, rt = blockIdx.x;
    const int r0 = w * 16;

    const float* Qg = g_Q + ((size_t)((b*8+h)*1024 + rt*128))*64;
    const float* Kg = g_K + ((size_t)((b*8+h)*1024))*64;
    const float* Vg = g_V + ((size_t)((b*8+h)*1024))*64;
    const float* Mg = mask + ((size_t)(h*1024 + rt*128))*1024;

    const uint32_t ps_a  = smem_u32(Ps);
    const uint32_t kv_a[2] = { smem_u32(KV0), smem_u32(KV1) };

    // ---- prologue: cp.async Q -> Ps, K/V chunk 0 -> buf0 ----
    {
        #pragma unroll
        for (int ii = 0; ii < 8; ii++){
            int idx = tid + ii*256;
            int r = idx >> 4, c = (idx & 15) << 2;
            CP_ASYNC16(ps_a + (uint32_t)(r*PS + c)*4, Qg + r*64 + c);
        }
        #pragma unroll
        for (int ii = 0; ii < 4; ii++){
            int idx = tid + ii*256;
            int r = idx >> 4, c = (idx & 15) << 2;
            CP_ASYNC16(kv_a[0] + (uint32_t)(r*QS + c)*4, Kg + r*64 + c);
            CP_ASYNC16(kv_a[0] + (uint32_t)(64*QS + r*VS + c)*4, Vg + r*64 + c);
        }
        CP_COMMIT();
    }

    unsigned q[8][4];
    float o[8][4];
    #pragma unroll
    for (int i=0;i<8;i++){ o[i][0]=0.f;o[i][1]=0.f;o[i][2]=0.f;o[i][3]=0.f; }
    float mrow0 = -1e30f, mrow1 = -1e30f, lrow0 = 0.f, lrow1 = 0.f;

    for (int jt = 0; jt < 16; jt++){
        CP_WAIT0();
        __syncthreads();          // jt's KV (and, at jt=0, Q) visible to all

        float* Kb = (jt & 1) ? KV1 : KV0;
        float* Vb = Kb + 64*QS;

        if (jt == 0){
            // lift Q fragments (warp-private rows of Ps; Ps reused for P below)
            #pragma unroll
            for (int ks = 0; ks < 8; ks++){
                int kb = ks*8;
                q[ks][0]=fu(Ps[(r0+gr  )*PS + kb+gc  ]);
                q[ks][1]=fu(Ps[(r0+gr+8)*PS + kb+gc  ]);
                q[ks][2]=fu(Ps[(r0+gr  )*PS + kb+gc+4]);
                q[ks][3]=fu(Ps[(r0+gr+8)*PS + kb+gc+4]);
            }
        }

        // prefetch next KV chunk into the other buffer (free: all warps are
        // past its last use, guaranteed by the barrier above)
        if (jt < 15){
            const float* kp = Kg + (jt+1)*64*64;
            const float* vp = Vg + (jt+1)*64*64;
            uint32_t dst = kv_a[(jt+1) & 1];
            #pragma unroll
            for (int ii = 0; ii < 4; ii++){
                int idx = tid + ii*256;
                int r = idx >> 4, c = (idx & 15) << 2;
                CP_ASYNC16(dst + (uint32_t)(r*QS + c)*4, kp + r*64 + c);
                CP_ASYNC16(dst + (uint32_t)(64*QS + r*VS + c)*4, vp + r*64 + c);
            }
            CP_COMMIT();
        }

        // ---- S = Q K^T : 16 rows x 64 cols (scale pre-folded into Q) ----
        float s[8][4];
        #pragma unroll
        for (int i=0;i<8;i++){ s[i][0]=0.f;s[i][1]=0.f;s[i][2]=0.f;s[i][3]=0.f; }
        #pragma unroll
        for (int ks=0; ks<8; ks++){
            int kb = ks*8;
            #pragma unroll
            for (int nt=0; nt<8; nt++){
                int n0 = nt*8;
                unsigned bb[2] = {
                    fu(Kb[(n0+gr)*QS + kb+gc  ]),
                    fu(Kb[(n0+gr)*QS + kb+gc+4]) };
                mma8(s[nt], q[ks], bb);
            }
        }

        // ---- online softmax ----
        float ml0 = -1e30f, ml1 = -1e30f;
        #pragma unroll
        for (int nt=0; nt<8; nt++){
            ml0 = fmaxf(ml0, fmaxf(s[nt][0], s[nt][1]));
            ml1 = fmaxf(ml1, fmaxf(s[nt][2], s[nt][3]));
        }
        ml0 = fmaxf(ml0, __shfl_xor_sync(0xffffffffu, ml0, 1));
        ml0 = fmaxf(ml0, __shfl_xor_sync(0xffffffffu, ml0, 2));
        ml1 = fmaxf(ml1, __shfl_xor_sync(0xffffffffu, ml1, 1));
        ml1 = fmaxf(ml1, __shfl_xor_sync(0xffffffffu, ml1, 2));
        float mn0 = fmaxf(mrow0, ml0), mn1 = fmaxf(mrow1, ml1);
        float al0 = __expf(mrow0 - mn0), al1 = __expf(mrow1 - mn1);
        mrow0 = mn0; mrow1 = mn1;

        float ls0 = 0.f, ls1 = 0.f;
        const float* mrp0 = Mg + (size_t)(r0+gr  )*1024 + jt*64;
        const float* mrp1 = Mg + (size_t)(r0+gr+8)*1024 + jt*64;
        #pragma unroll
        for (int nt=0; nt<8; nt++){
            int cc = nt*8 + 2*gc;
            float e0 = __expf(s[nt][0]-mn0), e1 = __expf(s[nt][1]-mn0);
            float e2 = __expf(s[nt][2]-mn1), e3 = __expf(s[nt][3]-mn1);
            ls0 += e0 + e1; ls1 += e2 + e3;
            float2 mk0 = *(const float2*)(mrp0 + cc);
            float2 mk1 = *(const float2*)(mrp1 + cc);
            *(float2*)(Ps + (r0+gr  )*PS + cc) =
                make_float2(tf32r(e0*mk0.x), tf32r(e1*mk0.y));
            *(float2*)(Ps + (r0+gr+8)*PS + cc) =
                make_float2(tf32r(e2*mk1.x), tf32r(e3*mk1.y));
        }
        lrow0 = lrow0*al0 + ls0;
        lrow1 = lrow1*al1 + ls1;
        #pragma unroll
        for (int nt=0; nt<8; nt++){
            o[nt][0]*=al0; o[nt][1]*=al0; o[nt][2]*=al1; o[nt][3]*=al1;
        }
        __syncwarp();   // Ps rows are warp-private

        // ---- O += P @ V ----
        #pragma unroll
        for (int ks=0; ks<8; ks++){
            int kb = ks*8;
            unsigned a[4] = {
                fu(Ps[(r0+gr  )*PS + kb+gc  ]),
                fu(Ps[(r0+gr+8)*PS + kb+gc  ]),
                fu(Ps[(r0+gr  )*PS + kb+gc+4]),
                fu(Ps[(r0+gr+8)*PS + kb+gc+4]) };
            #pragma unroll
            for (int nt=0; nt<8; nt++){
                int n0 = nt*8;
                unsigned bb[2] = {
                    fu(Vb[(kb+gc  )*VS + n0+gr]),
                    fu(Vb[(kb+gc+4)*VS + n0+gr]) };
                mma8(o[nt], a, bb);
            }
        }
        // no trailing barrier: next iteration's top barrier (after CP_WAIT0)
        // orders buffer reuse.
    }

    // finalize
    lrow0 += __shfl_xor_sync(0xffffffffu, lrow0, 1);
    lrow0 += __shfl_xor_sync(0xffffffffu, lrow0, 2);
    lrow1 += __shfl_xor_sync(0xffffffffu, lrow1, 1);
    lrow1 += __shfl_xor_sync(0xffffffffu, lrow1, 2);
    float inv0 = 1.f / lrow0, inv1 = 1.f / lrow1;

    float* Og = g_O + ((size_t)(b*1024 + rt*128))*512 + h*64;
    #pragma unroll
    for (int nt=0; nt<8; nt++){
        int d = nt*8 + 2*gc;
        *(float2*)(Og + (size_t)(r0+gr  )*512 + d) =
            make_float2(o[nt][0]*inv0, o[nt][1]*inv0);
        *(float2*)(Og + (size_t)(r0+gr+8)*512 + d) =
            make_float2(o[nt][2]*inv1, o[nt][3]*inv1);
    }
}

// ============================================================================
extern "C" void kernel_launch(void* const* d_in, const int* in_sizes, int n_in,
                              void* d_out, int out_size)
{
    (void)in_sizes; (void)n_in; (void)out_size;
    const float* x    = (const float*)d_in[0];
    const float* Wqkv = (const float*)d_in[1];
    const float* Wout = (const float*)d_in[2];
    const float* bout = (const float*)d_in[3];
    const float* mask = (const float*)d_in[4];
    float* out = (float*)d_out;

    cudaFuncSetAttribute(gemm256<1536,0>,
                         cudaFuncAttributeMaxDynamicSharedMemorySize, GEMM_SMEM);
    cudaFuncSetAttribute(gemm256<512,1>,
                         cudaFuncAttributeMaxDynamicSharedMemorySize, GEMM_SMEM);
    cudaFuncSetAttribute(attn_kernel,
                         cudaFuncAttributeMaxDynamicSharedMemorySize, ATT_SMEM);

    gemm256<1536,0><<<dim3(12, 128), 256, GEMM_SMEM>>>(x, Wqkv, nullptr, nullptr);
    attn_kernel<<<dim3(8, 8, 32), 256, ATT_SMEM>>>(mask);
    gemm256<512,1><<<dim3(4, 128), 256, GEMM_SMEM>>>(nullptr, Wout, bout, out);
}